// round 1
// baseline (speedup 1.0000x reference)
#include <cuda_runtime.h>

#define BB   128          // batch
#define TT   1024         // time steps
#define INF  64           // input features
#define HH   256          // hidden (both layers)
#define OUTF 64           // output features
#define NCTA 128
#define NTHR 256
#define K0   (INF + HH)   // 320
#define K1   (2 * HH)     // 512

// Persistent device state (static allocs are allowed; no cudaMalloc anywhere)
__device__ float    g_XT[TT * INF * BB];        // input transposed [t][i][b]  (~33.5 MB)
__device__ float    g_h0[2 * HH * BB];          // layer0 h, double buffered, [p][k][b]
__device__ float    g_h1[2 * HH * BB];          // layer1 h, double buffered
__device__ float    g_H1[TT * HH * BB];         // all layer1 h for deferred projection (~134 MB)
__device__ unsigned g_arrive = 0;               // monotonic grid-barrier counters (replay-safe)
__device__ unsigned g_release = 0;

__device__ __forceinline__ float sigf(float x) { return 1.0f / (1.0f + __expf(-x)); }

// Monotonic-ticket grid barrier. Safe across graph replays because counters only
// ever advance and each launch captures its own release base.
__device__ __forceinline__ void grid_bar(unsigned rel_base, unsigned& barn)
{
    __syncthreads();
    if (threadIdx.x == 0) {
        __threadfence();
        barn++;
        unsigned prev = atomicAdd(&g_arrive, 1u);
        if (((prev + 1u) & (NCTA - 1u)) == 0u) {
            atomicAdd(&g_release, 1u);          // last arriver releases
        } else {
            unsigned need = rel_base + barn;
            while ((int)(*(volatile unsigned*)&g_release - need) < 0) { }
        }
        __threadfence();
    }
    __syncthreads();
}

// 4-batch dot product: weights (SMEM row, broadcast) x activations ([k][b] global, LDG.128)
template <int LEN>
__device__ __forceinline__ void dot4(const float* __restrict__ wr,
                                     const float* __restrict__ act,
                                     int bb, float& a0, float& a1, float& a2, float& a3)
{
#pragma unroll 8
    for (int k = 0; k < LEN; k += 4) {
        const float4 wv = *reinterpret_cast<const float4*>(wr + k);
        const float4 v0 = __ldcg(reinterpret_cast<const float4*>(act + (k + 0) * BB + bb));
        const float4 v1 = __ldcg(reinterpret_cast<const float4*>(act + (k + 1) * BB + bb));
        const float4 v2 = __ldcg(reinterpret_cast<const float4*>(act + (k + 2) * BB + bb));
        const float4 v3 = __ldcg(reinterpret_cast<const float4*>(act + (k + 3) * BB + bb));
        a0 += wv.x * v0.x; a1 += wv.x * v0.y; a2 += wv.x * v0.z; a3 += wv.x * v0.w;
        a0 += wv.y * v1.x; a1 += wv.y * v1.y; a2 += wv.y * v1.z; a3 += wv.y * v1.w;
        a0 += wv.z * v2.x; a1 += wv.z * v2.y; a2 += wv.z * v2.z; a3 += wv.z * v2.w;
        a0 += wv.w * v3.x; a1 += wv.w * v3.y; a2 += wv.w * v3.z; a3 += wv.w * v3.w;
    }
}

// SMEM layout (floats):
//   [0 .. 16447]   loop: ws0 [8][320] + ws1 [8][512]   / proj: W_lin [64][256] + b_lin[64]
//   [16448 ..]     gb0 [8][128], gb1 [8][128], cst [4][128], bia0[8], bia1[8]
#define SM_FLOATS (16448 + 8 * BB + 8 * BB + 4 * BB + 16)
#define SM_BYTES  (SM_FLOATS * 4)

extern "C" __global__ void __launch_bounds__(NTHR, 1)
lstm_persistent_kernel(const float* __restrict__ input,
                       const float* __restrict__ W_ih0, const float* __restrict__ W_hh0,
                       const float* __restrict__ b_ih0, const float* __restrict__ b_hh0,
                       const float* __restrict__ W_ih1, const float* __restrict__ W_hh1,
                       const float* __restrict__ b_ih1, const float* __restrict__ b_hh1,
                       const float* __restrict__ W_lin, const float* __restrict__ b_lin,
                       float* __restrict__ out)
{
    extern __shared__ float sm[];
    float* ws0  = sm;                  // [8][K0]
    float* ws1  = sm + 8 * K0;         // [8][K1]
    float* gb0  = sm + 16448;          // [8][BB] layer0 gate values
    float* gb1  = gb0 + 8 * BB;        // [8][BB] layer1 gate values
    float* cst  = gb1 + 8 * BB;        // [4][BB]: c0 units {0,1}, c1 units {0,1}
    float* bia0 = cst + 4 * BB;        // [8]
    float* bia1 = bia0 + 8;            // [8]

    const int cta  = blockIdx.x;
    const int tid  = threadIdx.x;
    const int w    = tid >> 5;         // warp id 0..7 -> (gate = w>>1, unit_local = w&1)
    const int lane = tid & 31;
    const int gate = w >> 1;
    const int bb4  = lane * 4;         // this lane's 4 batch indices

    unsigned rel_base = *(volatile unsigned*)&g_release;   // quiescent at launch start
    unsigned barn = 0;

    // ---- Phase 0: init state, load weights, transpose input ----
    for (int i = tid; i < 4 * BB; i += NTHR) cst[i] = 0.f;
    for (int i = cta * NTHR + tid; i < 2 * HH * BB; i += NCTA * NTHR) {
        g_h0[i] = 0.f;
        g_h1[i] = 0.f;
    }
    for (int i = tid; i < 8 * K0; i += NTHR) {
        int rw = i / K0, k = i % K0;
        int r = (2 * cta + (rw & 1)) + (rw >> 1) * HH;
        ws0[i] = (k < INF) ? W_ih0[r * INF + k] : W_hh0[r * HH + (k - INF)];
    }
    for (int i = tid; i < 8 * K1; i += NTHR) {
        int rw = i / K1, k = i % K1;
        int r = (2 * cta + (rw & 1)) + (rw >> 1) * HH;
        ws1[i] = (k < HH) ? W_ih1[r * HH + k] : W_hh1[r * HH + (k - HH)];
    }
    if (tid < 8) {
        int r = (2 * cta + (tid & 1)) + (tid >> 1) * HH;
        bia0[tid] = b_ih0[r] + b_hh0[r];
        bia1[tid] = b_ih1[r] + b_hh1[r];
    }
    // transpose this CTA's 8 timesteps: XT[t][i][b] = input[b][t][i]
    for (int t = cta * 8; t < cta * 8 + 8; t++) {
        for (int i = tid; i < INF * BB; i += NTHR) {
            int ii = i >> 7, b = i & 127;
            g_XT[t * INF * BB + ii * BB + b] = input[(size_t)b * TT * INF + t * INF + ii];
        }
    }
    grid_bar(rel_base, barn);

    const float* wr0 = ws0 + w * K0;
    const float* wr1 = ws1 + w * K1;
    const int ule = tid >> 7;          // elementwise role: unit_local
    const int be  = tid & 127;         // elementwise role: batch

    // ---- Main loop: tick tau computes layer0(tau) and layer1(tau-1); ONE barrier/tick ----
    for (int tau = 0; tau <= TT; tau++) {
        const int pw = tau & 1;        // parity written this tick (h(tau))
        const int pr = pw ^ 1;         // parity holding h(tau-1)

        if (tau < TT) {
            // layer0 gates for step tau: [x_tau | h0(tau-1)] . w_row + b
            float a0 = 0.f, a1 = 0.f, a2 = 0.f, a3 = 0.f;
            dot4<INF>(wr0,        g_XT + tau * INF * BB, bb4, a0, a1, a2, a3);
            dot4<HH >(wr0 + INF,  g_h0 + pr * HH * BB,   bb4, a0, a1, a2, a3);
            const float bs = bia0[w];
            a0 += bs; a1 += bs; a2 += bs; a3 += bs;
            float4 r4;
            if (gate == 2) { r4.x = tanhf(a0); r4.y = tanhf(a1); r4.z = tanhf(a2); r4.w = tanhf(a3); }
            else           { r4.x = sigf(a0);  r4.y = sigf(a1);  r4.z = sigf(a2);  r4.w = sigf(a3);  }
            *reinterpret_cast<float4*>(gb0 + w * BB + bb4) = r4;
        }
        __syncthreads();
        if (tau < TT) {
            // layer0 elementwise: c0/h0 update for this CTA's 2 units
            const float iv = gb0[(0 + ule) * BB + be];
            const float fv = gb0[(2 + ule) * BB + be];
            const float gv = gb0[(4 + ule) * BB + be];
            const float ov = gb0[(6 + ule) * BB + be];
            const float c  = cst[ule * BB + be];
            const float cn = fv * c + iv * gv;
            cst[ule * BB + be] = cn;
            const float hn = ov * tanhf(cn);
            __stcg(&g_h0[pw * HH * BB + (2 * cta + ule) * BB + be], hn);
        }
        if (tau >= 1) {
            const int s = tau - 1;
            // layer1 gates for step s: [h0(s) | h1(s-1)]  (h0(s) is in parity pr, written last tick)
            float a0 = 0.f, a1 = 0.f, a2 = 0.f, a3 = 0.f;
            dot4<HH>(wr1,       g_h0 + pr * HH * BB, bb4, a0, a1, a2, a3);
            dot4<HH>(wr1 + HH,  g_h1 + pw * HH * BB, bb4, a0, a1, a2, a3);
            const float bs = bia1[w];
            a0 += bs; a1 += bs; a2 += bs; a3 += bs;
            float4 r4;
            if (gate == 2) { r4.x = tanhf(a0); r4.y = tanhf(a1); r4.z = tanhf(a2); r4.w = tanhf(a3); }
            else           { r4.x = sigf(a0);  r4.y = sigf(a1);  r4.z = sigf(a2);  r4.w = sigf(a3);  }
            *reinterpret_cast<float4*>(gb1 + w * BB + bb4) = r4;
            __syncthreads();
            const float iv = gb1[(0 + ule) * BB + be];
            const float fv = gb1[(2 + ule) * BB + be];
            const float gv = gb1[(4 + ule) * BB + be];
            const float ov = gb1[(6 + ule) * BB + be];
            const float c  = cst[(2 + ule) * BB + be];
            const float cn = fv * c + iv * gv;
            cst[(2 + ule) * BB + be] = cn;
            const float hn = ov * tanhf(cn);
            __stcg(&g_h1[pr * HH * BB + (2 * cta + ule) * BB + be], hn);
            __stcg(&g_H1[(size_t)s * HH * BB + (2 * cta + ule) * BB + be], hn);
        }
        grid_bar(rel_base, barn);
    }

    // ---- Final phase: deferred projection out[b][t][o] = h1(t) . W_lin[o] + b_lin[o] ----
    for (int i = tid; i < OUTF * HH; i += NTHR) sm[i] = W_lin[i];
    if (tid < OUTF) sm[OUTF * HH + tid] = b_lin[tid];
    __syncthreads();

    const int t = cta * 8 + w;                     // each warp owns one timestep
    const float* hb = g_H1 + (size_t)t * HH * BB;
    for (int ob = 0; ob < OUTF; ob += 8) {
        float acc[8][4];
#pragma unroll
        for (int oo = 0; oo < 8; oo++) { acc[oo][0] = acc[oo][1] = acc[oo][2] = acc[oo][3] = 0.f; }
        for (int j = 0; j < HH; j++) {
            const float4 hv = *reinterpret_cast<const float4*>(hb + j * BB + bb4);
#pragma unroll
            for (int oo = 0; oo < 8; oo++) {
                const float wv = sm[(ob + oo) * HH + j];
                acc[oo][0] += wv * hv.x; acc[oo][1] += wv * hv.y;
                acc[oo][2] += wv * hv.z; acc[oo][3] += wv * hv.w;
            }
        }
#pragma unroll
        for (int oo = 0; oo < 8; oo++) {
            const int o = ob + oo;
            const float bl = sm[OUTF * HH + o];
            out[(size_t)(bb4 + 0) * TT * OUTF + t * OUTF + o] = acc[oo][0] + bl;
            out[(size_t)(bb4 + 1) * TT * OUTF + t * OUTF + o] = acc[oo][1] + bl;
            out[(size_t)(bb4 + 2) * TT * OUTF + t * OUTF + o] = acc[oo][2] + bl;
            out[(size_t)(bb4 + 3) * TT * OUTF + t * OUTF + o] = acc[oo][3] + bl;
        }
    }
}

extern "C" void kernel_launch(void* const* d_in, const int* in_sizes, int n_in,
                              void* d_out, int out_size)
{
    (void)in_sizes; (void)n_in; (void)out_size;
    cudaFuncSetAttribute(lstm_persistent_kernel,
                         cudaFuncAttributeMaxDynamicSharedMemorySize, SM_BYTES);
    lstm_persistent_kernel<<<NCTA, NTHR, SM_BYTES>>>(
        (const float*)d_in[0],
        (const float*)d_in[1], (const float*)d_in[2],
        (const float*)d_in[3], (const float*)d_in[4],
        (const float*)d_in[5], (const float*)d_in[6],
        (const float*)d_in[7], (const float*)d_in[8],
        (const float*)d_in[9], (const float*)d_in[10],
        (float*)d_out);
}

// round 2
// speedup vs baseline: 1.2359x; 1.2359x over previous
#include <cuda_runtime.h>

#define BB   128          // batch
#define TT   1024         // time steps
#define INF  64           // input features
#define HH   256          // hidden (both layers)
#define OUTF 64           // output features
#define NCTA 128
#define NTHR 256
#define K0   (INF + HH)   // 320
#define K1   (2 * HH)     // 512

typedef unsigned long long ull;

// Persistent device state (static allocs allowed; no cudaMalloc anywhere)
__device__ float    g_XT[TT * INF * BB];        // input transposed [t][i][b]
__device__ float    g_h0[2 * HH * BB];          // layer0 h double-buffered [p][k][b]
__device__ float    g_h1[2 * HH * BB];          // layer1 h double-buffered
__device__ float    g_H1[TT * HH * BB];         // all layer1 h for deferred projection
__device__ unsigned g_arrive = 0;               // monotonic barrier counters (replay-safe)
__device__ unsigned g_release = 0;

__device__ __forceinline__ float sigf(float x) { return 1.0f / (1.0f + __expf(-x)); }

__device__ __forceinline__ void grid_bar(unsigned rel_base, unsigned& barn)
{
    __syncthreads();
    if (threadIdx.x == 0) {
        __threadfence();
        barn++;
        unsigned prev = atomicAdd(&g_arrive, 1u);
        if (((prev + 1u) & (NCTA - 1u)) == 0u) {
            atomicAdd(&g_release, 1u);
        } else {
            unsigned need = rel_base + barn;
            while ((int)(*(volatile unsigned*)&g_release - need) < 0) { }
        }
        __threadfence();
    }
    __syncthreads();
}

// packed dual fp32 FMA: acc(lo,hi) += a(lo,hi) * b(lo,hi)
__device__ __forceinline__ void fma2(ull& acc, ull a, ull b)
{
    asm("fma.rn.f32x2 %0, %1, %2, %0;" : "+l"(acc) : "l"(a), "l"(b));
}

// Inner GEMM segment: 4 gate rows x 2 batch cols per lane.
// wk: SMEM weights, layout [k][2 x ulonglong2] (4 pre-splatted float2 rows per k)
// act: global activations [k][BB]; c0 = first batch col for this lane (even)
template <int K>
__device__ __forceinline__ void gemm_seg(const ulonglong2* __restrict__ wk,
                                         const float* __restrict__ act, int c0,
                                         ull& a0, ull& a1, ull& a2, ull& a3)
{
#pragma unroll 8
    for (int k = 0; k < K; k++) {
        const ull act2 = __ldcg(reinterpret_cast<const ull*>(act + k * BB + c0));
        const ulonglong2 wA = wk[2 * k];
        const ulonglong2 wB = wk[2 * k + 1];
        fma2(a0, act2, wA.x);
        fma2(a1, act2, wA.y);
        fma2(a2, act2, wB.x);
        fma2(a3, act2, wB.y);
    }
}

// SMEM layout (floats):
//   ws0:   [0      .. 10239]   4 warps x K0 x 4 rows x float2(splat)
//   ws1:   [10240  .. 26623]   4 warps x K1 x 4 rows x float2(splat)
//   gb0:   [26624  .. 27647]   [4 gates][4 units][64 cols]
//   gb1:   [27648  .. 28671]
//   cst:   [28672  .. 29183]   [2 layers][4 units][64 cols]
//   bia:   [29184  .. 29215]   [8 warp-slots][4 rows]
#define OFS_WS0 0
#define OFS_WS1 10240
#define OFS_GB0 26624
#define OFS_GB1 27648
#define OFS_CST 28672
#define OFS_BIA 29184
#define SM_FLOATS 29216
#define SM_BYTES  (SM_FLOATS * 4)

extern "C" __global__ void __launch_bounds__(NTHR, 1)
lstm_persistent_kernel(const float* __restrict__ input,
                       const float* __restrict__ W_ih0, const float* __restrict__ W_hh0,
                       const float* __restrict__ b_ih0, const float* __restrict__ b_hh0,
                       const float* __restrict__ W_ih1, const float* __restrict__ W_hh1,
                       const float* __restrict__ b_ih1, const float* __restrict__ b_hh1,
                       const float* __restrict__ W_lin, const float* __restrict__ b_lin,
                       float* __restrict__ out)
{
    extern __shared__ float sm[];
    float2* ws0f2 = reinterpret_cast<float2*>(sm + OFS_WS0);
    float2* ws1f2 = reinterpret_cast<float2*>(sm + OFS_WS1);
    float*  gb0   = sm + OFS_GB0;
    float*  gb1   = sm + OFS_GB1;
    float*  cst   = sm + OFS_CST;
    float*  bia   = sm + OFS_BIA;

    const int cta  = blockIdx.x;
    const int tid  = threadIdx.x;
    const int w    = tid >> 5;         // 0..3 layer0 gates, 4..7 layer1 gates
    const int lane = tid & 31;
    const int rg4  = (cta >> 1) * 4;   // first unit of this CTA's 4-unit group
    const int ch   = cta & 1;          // batch col half
    const int c0   = ch * 64 + 2 * lane;

    unsigned rel_base = *(volatile unsigned*)&g_release;
    unsigned barn = 0;

    // ---- Phase 0: init state, load + splat weights, transpose input ----
    for (int i = tid; i < 2 * 4 * 64; i += NTHR) cst[i] = 0.f;
    for (int i = cta * NTHR + tid; i < 2 * HH * BB; i += NCTA * NTHR) {
        g_h0[i] = 0.f;
        g_h1[i] = 0.f;
    }
    for (int i = tid; i < 4 * K0 * 4; i += NTHR) {
        int wq = i / (4 * K0), r = i & 3, k = (i >> 2) % K0;
        int row = wq * HH + rg4 + r;
        float v = (k < INF) ? W_ih0[row * INF + k] : W_hh0[row * HH + (k - INF)];
        ws0f2[i] = make_float2(v, v);
    }
    for (int i = tid; i < 4 * K1 * 4; i += NTHR) {
        int wq = i / (4 * K1), r = i & 3, k = (i >> 2) % K1;
        int row = wq * HH + rg4 + r;
        float v = (k < HH) ? W_ih1[row * HH + k] : W_hh1[row * HH + (k - HH)];
        ws1f2[i] = make_float2(v, v);
    }
    if (tid < 32) {
        int wq = tid >> 2, r = tid & 3;
        if (wq < 4) {
            int row = wq * HH + rg4 + r;
            bia[tid] = b_ih0[row] + b_hh0[row];
        } else {
            int row = (wq - 4) * HH + rg4 + r;
            bia[tid] = b_ih1[row] + b_hh1[row];
        }
    }
    // transpose this CTA's 8 timesteps: XT[t][i][b] = input[b][t][i]
    for (int t = cta * 8; t < cta * 8 + 8; t++) {
        for (int i = tid; i < INF * BB; i += NTHR) {
            int ii = i >> 7, b = i & 127;
            g_XT[t * INF * BB + ii * BB + b] = input[(size_t)b * TT * INF + t * INF + ii];
        }
    }
    grid_bar(rel_base, barn);

    const ulonglong2* wk0 = reinterpret_cast<const ulonglong2*>(ws0f2 + (size_t)w * K0 * 4);
    const ulonglong2* wk1 = reinterpret_cast<const ulonglong2*>(ws1f2 + (size_t)(w - 4) * K1 * 4);
    const int eu = tid >> 6;           // elementwise: unit 0..3
    const int ec = tid & 63;           // elementwise: col 0..63
    const int eg = ch * 64 + ec;       // global batch col

    // ---- Main loop: tick tau = layer0(tau) + layer1(tau-1); one barrier/tick ----
    for (int tau = 0; tau <= TT; tau++) {
        const int pw = tau & 1;
        const int pr = pw ^ 1;

        if (w < 4) {
            if (tau < TT) {
                ull a0 = 0, a1 = 0, a2 = 0, a3 = 0;
                gemm_seg<INF>(wk0,           g_XT + tau * INF * BB, c0, a0, a1, a2, a3);
                gemm_seg<HH >(wk0 + INF * 2, g_h0 + pr * HH * BB,   c0, a0, a1, a2, a3);
                ull accs[4] = {a0, a1, a2, a3};
#pragma unroll
                for (int r = 0; r < 4; r++) {
                    float lo = __uint_as_float((unsigned)accs[r]) + bia[w * 4 + r];
                    float hi = __uint_as_float((unsigned)(accs[r] >> 32)) + bia[w * 4 + r];
                    float2 o;
                    if (w == 2) { o.x = tanhf(lo); o.y = tanhf(hi); }
                    else        { o.x = sigf(lo);  o.y = sigf(hi);  }
                    *reinterpret_cast<float2*>(gb0 + (w * 4 + r) * 64 + 2 * lane) = o;
                }
            }
        } else {
            if (tau >= 1) {
                const int gq = w - 4;
                ull a0 = 0, a1 = 0, a2 = 0, a3 = 0;
                gemm_seg<HH>(wk1,          g_h0 + pr * HH * BB, c0, a0, a1, a2, a3);
                gemm_seg<HH>(wk1 + HH * 2, g_h1 + pw * HH * BB, c0, a0, a1, a2, a3);
                ull accs[4] = {a0, a1, a2, a3};
#pragma unroll
                for (int r = 0; r < 4; r++) {
                    float lo = __uint_as_float((unsigned)accs[r]) + bia[w * 4 + r];
                    float hi = __uint_as_float((unsigned)(accs[r] >> 32)) + bia[w * 4 + r];
                    float2 o;
                    if (gq == 2) { o.x = tanhf(lo); o.y = tanhf(hi); }
                    else         { o.x = sigf(lo);  o.y = sigf(hi);  }
                    *reinterpret_cast<float2*>(gb1 + (gq * 4 + r) * 64 + 2 * lane) = o;
                }
            }
        }
        __syncthreads();

        // elementwise: each thread owns (unit eu, col ec) for both layers
        if (tau < TT) {
            const float iv = gb0[(0 * 4 + eu) * 64 + ec];
            const float fv = gb0[(1 * 4 + eu) * 64 + ec];
            const float gv = gb0[(2 * 4 + eu) * 64 + ec];
            const float ov = gb0[(3 * 4 + eu) * 64 + ec];
            const float c  = cst[eu * 64 + ec];
            const float cn = fv * c + iv * gv;
            cst[eu * 64 + ec] = cn;
            __stcg(&g_h0[pw * HH * BB + (rg4 + eu) * BB + eg], ov * tanhf(cn));
        }
        if (tau >= 1) {
            const int s = tau - 1;
            const float iv = gb1[(0 * 4 + eu) * 64 + ec];
            const float fv = gb1[(1 * 4 + eu) * 64 + ec];
            const float gv = gb1[(2 * 4 + eu) * 64 + ec];
            const float ov = gb1[(3 * 4 + eu) * 64 + ec];
            const float c  = cst[(4 + eu) * 64 + ec];
            const float cn = fv * c + iv * gv;
            cst[(4 + eu) * 64 + ec] = cn;
            const float hn = ov * tanhf(cn);
            __stcg(&g_h1[pr * HH * BB + (rg4 + eu) * BB + eg], hn);
            __stcg(&g_H1[(size_t)s * HH * BB + (rg4 + eu) * BB + eg], hn);
        }
        grid_bar(rel_base, barn);
    }

    // ---- Deferred projection: out[b][t][o] = h1(t) . W_lin[o] + b_lin[o] ----
    for (int i = tid; i < OUTF * HH; i += NTHR) sm[i] = W_lin[i];
    if (tid < OUTF) sm[OUTF * HH + tid] = b_lin[tid];
    __syncthreads();

    const int t = cta * 8 + w;                     // each warp owns one timestep
    const int bb4 = lane * 4;
    const float* hb = g_H1 + (size_t)t * HH * BB;
    for (int ob = 0; ob < OUTF; ob += 8) {
        float acc[8][4];
#pragma unroll
        for (int oo = 0; oo < 8; oo++) { acc[oo][0] = acc[oo][1] = acc[oo][2] = acc[oo][3] = 0.f; }
        for (int j = 0; j < HH; j++) {
            const float4 hv = *reinterpret_cast<const float4*>(hb + j * BB + bb4);
#pragma unroll
            for (int oo = 0; oo < 8; oo++) {
                const float wv = sm[(ob + oo) * HH + j];
                acc[oo][0] += wv * hv.x; acc[oo][1] += wv * hv.y;
                acc[oo][2] += wv * hv.z; acc[oo][3] += wv * hv.w;
            }
        }
#pragma unroll
        for (int oo = 0; oo < 8; oo++) {
            const int o = ob + oo;
            const float bl = sm[OUTF * HH + o];
            out[(size_t)(bb4 + 0) * TT * OUTF + t * OUTF + o] = acc[oo][0] + bl;
            out[(size_t)(bb4 + 1) * TT * OUTF + t * OUTF + o] = acc[oo][1] + bl;
            out[(size_t)(bb4 + 2) * TT * OUTF + t * OUTF + o] = acc[oo][2] + bl;
            out[(size_t)(bb4 + 3) * TT * OUTF + t * OUTF + o] = acc[oo][3] + bl;
        }
    }
}

extern "C" void kernel_launch(void* const* d_in, const int* in_sizes, int n_in,
                              void* d_out, int out_size)
{
    (void)in_sizes; (void)n_in; (void)out_size;
    cudaFuncSetAttribute(lstm_persistent_kernel,
                         cudaFuncAttributeMaxDynamicSharedMemorySize, SM_BYTES);
    lstm_persistent_kernel<<<NCTA, NTHR, SM_BYTES>>>(
        (const float*)d_in[0],
        (const float*)d_in[1], (const float*)d_in[2],
        (const float*)d_in[3], (const float*)d_in[4],
        (const float*)d_in[5], (const float*)d_in[6],
        (const float*)d_in[7], (const float*)d_in[8],
        (const float*)d_in[9], (const float*)d_in[10],
        (float*)d_out);
}

// round 5
// speedup vs baseline: 1.9492x; 1.5772x over previous
#include <cuda_runtime.h>

#define BB   128          // batch
#define TT   1024         // time steps
#define INF  64           // input features
#define HH   256          // hidden (both layers)
#define OUTF 64           // output features
#define NCTA 128
#define NTHR 256
#define K0   (INF + HH)   // 320
#define K1   (2 * HH)     // 512

typedef unsigned long long ull;

// Persistent device state (static allocs allowed; no cudaMalloc anywhere)
__device__ __align__(16) float g_XT[TT * INF * BB];   // input transposed [t][i][b]
__device__ __align__(16) float g_h0[2 * HH * BB];     // layer0 h double-buffered [p][k][b]
__device__ __align__(16) float g_h1[2 * HH * BB];     // layer1 h double-buffered
__device__ __align__(16) float g_H1[TT * HH * BB];    // all layer1 h (deferred projection)
__device__ unsigned g_arrive = 0;                     // PROVEN round-2 barrier counters
__device__ unsigned g_release = 0;

__device__ __forceinline__ float sigf(float x) { return 1.0f / (1.0f + __expf(-x)); }

// PROVEN round-2 monotonic-ticket grid barrier (unchanged, byte-exact semantics).
__device__ __forceinline__ void grid_bar(unsigned rel_base, unsigned& barn)
{
    __syncthreads();
    if (threadIdx.x == 0) {
        __threadfence();
        barn++;
        unsigned prev = atomicAdd(&g_arrive, 1u);
        if (((prev + 1u) & (NCTA - 1u)) == 0u) {
            atomicAdd(&g_release, 1u);
        } else {
            unsigned need = rel_base + barn;
            while ((int)(*(volatile unsigned*)&g_release - need) < 0) { }
        }
        __threadfence();
    }
    __syncthreads();
}

// packed dual fp32 FMA: acc(lo,hi) += a(lo,hi) * b(lo,hi)
__device__ __forceinline__ void fma2(ull& acc, ull a, ull b)
{
    asm("fma.rn.f32x2 %0, %1, %2, %0;" : "+l"(acc) : "l"(a), "l"(b));
}
// splat float into both halves of a 64-bit pair (ALU pipe)
__device__ __forceinline__ ull pk(float x)
{
    ull r; asm("mov.b64 %0, {%1, %1};" : "=l"(r) : "f"(x)); return r;
}

// Inner GEMM: 8 gate rows x 4 cols/lane (128 cols/warp), k in [ks,ke).
// ws4: SMEM weights float4[k][2] (rows 0..3, 4..7), act: [k-koff][BB] global.
__device__ __forceinline__ void gemm_seg(ull* accA, ull* accB,
                                         const float4* __restrict__ ws4,
                                         int ks, int ke,
                                         const float* __restrict__ act, int koff, int lane)
{
    const ulonglong2* ap = reinterpret_cast<const ulonglong2*>(act) + lane;
#pragma unroll 4
    for (int k = ks; k < ke; k++) {
        const ulonglong2 a = __ldcg(ap + (k - koff) * (BB / 4));
        const float4 wlo = ws4[k * 2 + 0];
        const float4 whi = ws4[k * 2 + 1];
        const ull w0 = pk(wlo.x), w1 = pk(wlo.y), w2 = pk(wlo.z), w3 = pk(wlo.w);
        const ull w4 = pk(whi.x), w5 = pk(whi.y), w6 = pk(whi.z), w7 = pk(whi.w);
        fma2(accA[0], a.x, w0); fma2(accB[0], a.y, w0);
        fma2(accA[1], a.x, w1); fma2(accB[1], a.y, w1);
        fma2(accA[2], a.x, w2); fma2(accB[2], a.y, w2);
        fma2(accA[3], a.x, w3); fma2(accB[3], a.y, w3);
        fma2(accA[4], a.x, w4); fma2(accB[4], a.y, w4);
        fma2(accA[5], a.x, w5); fma2(accB[5], a.y, w5);
        fma2(accA[6], a.x, w6); fma2(accB[6], a.y, w6);
        fma2(accA[7], a.x, w7); fma2(accB[7], a.y, w7);
    }
}

// SMEM layout (floats):
#define OFS_WS0 0                      // [K0][8]   layer0 weights (rows = gate*2+unit)
#define OFS_WS1 (K0 * 8)               // [K1][8]   layer1 weights            (2560)
#define OFS_P0  (OFS_WS1 + K1 * 8)     // [4 kq][8 r][128 c] layer0 partials  (6656)
#define OFS_P1  (OFS_P0 + 4096)        // layer1 partials                    (10752)
#define OFS_CST (OFS_P1 + 4096)        // [2 l][2 u][128 c] cell state       (14848)
#define OFS_BIA (OFS_CST + 512)        // [2 l][8 r] biases                  (15360)
#define SM_FLOATS 16512                // also covers projection phase (16448)
#define SM_BYTES  (SM_FLOATS * 4)

extern "C" __global__ void __launch_bounds__(NTHR, 1)
lstm_persistent_kernel(const float* __restrict__ input,
                       const float* __restrict__ W_ih0, const float* __restrict__ W_hh0,
                       const float* __restrict__ b_ih0, const float* __restrict__ b_hh0,
                       const float* __restrict__ W_ih1, const float* __restrict__ W_hh1,
                       const float* __restrict__ b_ih1, const float* __restrict__ b_hh1,
                       const float* __restrict__ W_lin, const float* __restrict__ b_lin,
                       float* __restrict__ out)
{
    extern __shared__ float sm[];
    const int cta  = blockIdx.x;
    const int tid  = threadIdx.x;
    const int w    = tid >> 5;
    const int lane = tid & 31;

    unsigned rel_base = *(volatile unsigned*)&g_release;   // quiescent at launch start
    unsigned barn = 0;

    // ---- Phase 0: init state, stage weights, transpose input ----
    for (int i = tid; i < 512; i += NTHR) sm[OFS_CST + i] = 0.f;
    for (int i = cta * NTHR + tid; i < 2 * HH * BB; i += NCTA * NTHR) {
        g_h0[i] = 0.f;
        g_h1[i] = 0.f;
    }
    // ws0[k*8 + r] = W0[(r>>1)*HH + 2*cta + (r&1)][k], k<INF from W_ih0 else W_hh0
    for (int i = tid; i < K0 * 8; i += NTHR) {
        int k = i >> 3, r = i & 7;
        int row = (r >> 1) * HH + 2 * cta + (r & 1);
        sm[OFS_WS0 + i] = (k < INF) ? W_ih0[row * INF + k] : W_hh0[row * HH + (k - INF)];
    }
    for (int i = tid; i < K1 * 8; i += NTHR) {
        int k = i >> 3, r = i & 7;
        int row = (r >> 1) * HH + 2 * cta + (r & 1);
        sm[OFS_WS1 + i] = (k < HH) ? W_ih1[row * HH + k] : W_hh1[row * HH + (k - HH)];
    }
    if (tid < 16) {
        int l = tid >> 3, r = tid & 7;
        int row = (r >> 1) * HH + 2 * cta + (r & 1);
        sm[OFS_BIA + tid] = l ? (b_ih1[row] + b_hh1[row]) : (b_ih0[row] + b_hh0[row]);
    }
    // transpose this CTA's 8 timesteps: XT[t][i][b] = input[b][t][i]
    for (int t = cta * 8; t < cta * 8 + 8; t++) {
        for (int i = tid; i < INF * BB; i += NTHR) {
            int ii = i >> 7, b = i & 127;
            g_XT[t * INF * BB + ii * BB + b] = input[(size_t)b * TT * INF + t * INF + ii];
        }
    }
    grid_bar(rel_base, barn);

    const float4* ws4 = reinterpret_cast<const float4*>(sm + ((w < 4) ? OFS_WS0 : OFS_WS1));
    float* pbase = sm + ((w < 4) ? OFS_P0 : OFS_P1) + (w & 3) * 1024;  // [kq][r][c]

    // ew role: tid<128: layer l, unit j, 4 cols starting c
    const int el = tid >> 6;
    const int ej = (tid >> 5) & 1;
    const int ec = (tid & 31) * 4;

    // ---- Main loop: tick tau = layer0(tau) + layer1(tau-1); one barrier/tick ----
    for (int tau = 0; tau <= TT; tau++) {
        const int pw = tau & 1;
        const int pr = pw ^ 1;

        ull accA[8], accB[8];
#pragma unroll
        for (int r = 0; r < 8; r++) { accA[r] = 0ull; accB[r] = 0ull; }

        bool did = false;
        if (w < 4) {
            if (tau < TT) {
                did = true;
                const int ks = w * 80, ke = ks + 80;
                if (ks < INF)   // warp 0: x segment then h0 segment
                    gemm_seg(accA, accB, ws4, ks, min(ke, INF),
                             g_XT + tau * INF * BB, 0, lane);
                if (ke > INF)
                    gemm_seg(accA, accB, ws4, max(ks, INF), ke,
                             g_h0 + pr * HH * BB, INF, lane);
            }
        } else {
            if (tau >= 1) {
                did = true;
                const int kq = w - 4;
                const int ks = kq * 128, ke = ks + 128;
                if (kq < 2)     // h0(tau-1) half
                    gemm_seg(accA, accB, ws4, ks, ke, g_h0 + pr * HH * BB, 0, lane);
                else            // h1(tau-2) half
                    gemm_seg(accA, accB, ws4, ks, ke, g_h1 + pw * HH * BB, HH, lane);
            }
        }
        if (did) {
#pragma unroll
            for (int r = 0; r < 8; r++) {
                ulonglong2 v; v.x = accA[r]; v.y = accB[r];
                *reinterpret_cast<ulonglong2*>(pbase + r * 128 + 4 * lane) = v;
            }
        }
        __syncthreads();

        // elementwise: combine 4 k-partials, apply gates, update c/h
        if (tid < 128) {
            const bool doit = (el == 0) ? (tau < TT) : (tau >= 1);
            if (doit) {
                const float* pb = sm + (el ? OFS_P1 : OFS_P0);
                float4 gs[4];
#pragma unroll
                for (int g = 0; g < 4; g++) {
                    const int roff = (g * 2 + ej) * 128 + ec;
                    float4 s0 = *reinterpret_cast<const float4*>(pb + 0 * 1024 + roff);
                    float4 s1 = *reinterpret_cast<const float4*>(pb + 1 * 1024 + roff);
                    float4 s2 = *reinterpret_cast<const float4*>(pb + 2 * 1024 + roff);
                    float4 s3 = *reinterpret_cast<const float4*>(pb + 3 * 1024 + roff);
                    const float bv = sm[OFS_BIA + el * 8 + g * 2 + ej];
                    gs[g].x = s0.x + s1.x + s2.x + s3.x + bv;
                    gs[g].y = s0.y + s1.y + s2.y + s3.y + bv;
                    gs[g].z = s0.z + s1.z + s2.z + s3.z + bv;
                    gs[g].w = s0.w + s1.w + s2.w + s3.w + bv;
                }
                float4 c_old = *reinterpret_cast<float4*>(sm + OFS_CST + (el * 2 + ej) * 128 + ec);
                float4 cn, hn;
                cn.x = sigf(gs[1].x) * c_old.x + sigf(gs[0].x) * tanhf(gs[2].x);
                cn.y = sigf(gs[1].y) * c_old.y + sigf(gs[0].y) * tanhf(gs[2].y);
                cn.z = sigf(gs[1].z) * c_old.z + sigf(gs[0].z) * tanhf(gs[2].z);
                cn.w = sigf(gs[1].w) * c_old.w + sigf(gs[0].w) * tanhf(gs[2].w);
                *reinterpret_cast<float4*>(sm + OFS_CST + (el * 2 + ej) * 128 + ec) = cn;
                hn.x = sigf(gs[3].x) * tanhf(cn.x);
                hn.y = sigf(gs[3].y) * tanhf(cn.y);
                hn.z = sigf(gs[3].z) * tanhf(cn.z);
                hn.w = sigf(gs[3].w) * tanhf(cn.w);
                const int row = 2 * cta + ej;
                if (el == 0) {
                    __stcg(reinterpret_cast<float4*>(g_h0 + pw * HH * BB + row * BB + ec), hn);
                } else {
                    __stcg(reinterpret_cast<float4*>(g_h1 + pr * HH * BB + row * BB + ec), hn);
                    __stcg(reinterpret_cast<float4*>(g_H1 + (size_t)(tau - 1) * HH * BB + row * BB + ec), hn);
                }
            }
        }
        grid_bar(rel_base, barn);
    }

    // ---- Deferred projection: out[b][t][o] = h1(t) . W_lin[o] + b_lin[o] ----
    for (int i = tid; i < OUTF * HH; i += NTHR) sm[i] = W_lin[i];
    if (tid < OUTF) sm[OUTF * HH + tid] = b_lin[tid];
    __syncthreads();

    const int t = cta * 8 + w;                     // each warp owns one timestep
    const int bb4 = lane * 4;
    const float* hb = g_H1 + (size_t)t * HH * BB;
    for (int ob = 0; ob < OUTF; ob += 8) {
        float acc[8][4];
#pragma unroll
        for (int oo = 0; oo < 8; oo++) { acc[oo][0] = acc[oo][1] = acc[oo][2] = acc[oo][3] = 0.f; }
        for (int j = 0; j < HH; j++) {
            const float4 hv = *reinterpret_cast<const float4*>(hb + j * BB + bb4);
#pragma unroll
            for (int oo = 0; oo < 8; oo++) {
                const float wv = sm[(ob + oo) * HH + j];
                acc[oo][0] += wv * hv.x; acc[oo][1] += wv * hv.y;
                acc[oo][2] += wv * hv.z; acc[oo][3] += wv * hv.w;
            }
        }
#pragma unroll
        for (int oo = 0; oo < 8; oo++) {
            const int o = ob + oo;
            const float bl = sm[OUTF * HH + o];
            out[(size_t)(bb4 + 0) * TT * OUTF + t * OUTF + o] = acc[oo][0] + bl;
            out[(size_t)(bb4 + 1) * TT * OUTF + t * OUTF + o] = acc[oo][1] + bl;
            out[(size_t)(bb4 + 2) * TT * OUTF + t * OUTF + o] = acc[oo][2] + bl;
            out[(size_t)(bb4 + 3) * TT * OUTF + t * OUTF + o] = acc[oo][3] + bl;
        }
    }
}

extern "C" void kernel_launch(void* const* d_in, const int* in_sizes, int n_in,
                              void* d_out, int out_size)
{
    (void)in_sizes; (void)n_in; (void)out_size;
    cudaFuncSetAttribute(lstm_persistent_kernel,
                         cudaFuncAttributeMaxDynamicSharedMemorySize, SM_BYTES);
    lstm_persistent_kernel<<<NCTA, NTHR, SM_BYTES>>>(
        (const float*)d_in[0],
        (const float*)d_in[1], (const float*)d_in[2],
        (const float*)d_in[3], (const float*)d_in[4],
        (const float*)d_in[5], (const float*)d_in[6],
        (const float*)d_in[7], (const float*)d_in[8],
        (const float*)d_in[9], (const float*)d_in[10],
        (float*)d_out);
}

// round 6
// speedup vs baseline: 2.7527x; 1.4122x over previous
#include <cuda_runtime.h>

#define BB   128          // batch
#define TT   1024         // time steps
#define INF  64           // input features
#define HH   256          // hidden (both layers)
#define OUTF 64           // output features
#define NCTA 128
#define NTHR 512
#define K0   (INF + HH)   // 320
#define K1   (2 * HH)     // 512

typedef unsigned long long ull;

// Persistent device state (static allocs allowed; no cudaMalloc anywhere)
__device__ __align__(16) float g_XT[TT * INF * BB];   // input transposed [t][i][b]
__device__ __align__(16) float g_h0[2 * HH * BB];     // layer0 h double-buffered [p][k][b]
__device__ __align__(16) float g_h1[2 * HH * BB];     // layer1 h double-buffered
__device__ __align__(16) float g_H1[TT * HH * BB];    // all layer1 h (deferred projection)
__device__ unsigned g_arrive = 0;                     // PROVEN ticket-barrier counters
__device__ unsigned g_release = 0;

__device__ __forceinline__ float sigf(float x) { return 1.0f / (1.0f + __expf(-x)); }

// PROVEN monotonic-ticket grid barrier (byte-exact semantics from the passing kernels).
__device__ __forceinline__ void grid_bar(unsigned rel_base, unsigned& barn)
{
    __syncthreads();
    if (threadIdx.x == 0) {
        __threadfence();
        barn++;
        unsigned prev = atomicAdd(&g_arrive, 1u);
        if (((prev + 1u) & (NCTA - 1u)) == 0u) {
            atomicAdd(&g_release, 1u);
        } else {
            unsigned need = rel_base + barn;
            while ((int)(*(volatile unsigned*)&g_release - need) < 0) { }
        }
        __threadfence();
    }
    __syncthreads();
}

// packed dual fp32 FMA: acc(lo,hi) += a(lo,hi) * b(lo,hi)
__device__ __forceinline__ void fma2(ull& acc, ull a, ull b)
{
    asm("fma.rn.f32x2 %0, %1, %2, %0;" : "+l"(acc) : "l"(a), "l"(b));
}
// splat float into both halves of a 64-bit pair (ALU pipe)
__device__ __forceinline__ ull pk(float x)
{
    ull r; asm("mov.b64 %0, {%1, %1};" : "=l"(r) : "f"(x)); return r;
}

// Inner GEMM: 8 gate rows x 4 cols/lane (128 cols/warp), k in [ks,ke).
// ws4: SMEM weights float4[k][2] (rows 0..3, 4..7), act: [k-koff][BB] global.
__device__ __forceinline__ void gemm_seg(ull* accA, ull* accB,
                                         const float4* __restrict__ ws4,
                                         int ks, int ke,
                                         const float* __restrict__ act, int koff, int lane)
{
    const ulonglong2* ap = reinterpret_cast<const ulonglong2*>(act) + lane;
#pragma unroll 4
    for (int k = ks; k < ke; k++) {
        const ulonglong2 a = __ldcg(ap + (k - koff) * (BB / 4));
        const float4 wlo = ws4[k * 2 + 0];
        const float4 whi = ws4[k * 2 + 1];
        const ull w0 = pk(wlo.x), w1 = pk(wlo.y), w2 = pk(wlo.z), w3 = pk(wlo.w);
        const ull w4 = pk(whi.x), w5 = pk(whi.y), w6 = pk(whi.z), w7 = pk(whi.w);
        fma2(accA[0], a.x, w0); fma2(accB[0], a.y, w0);
        fma2(accA[1], a.x, w1); fma2(accB[1], a.y, w1);
        fma2(accA[2], a.x, w2); fma2(accB[2], a.y, w2);
        fma2(accA[3], a.x, w3); fma2(accB[3], a.y, w3);
        fma2(accA[4], a.x, w4); fma2(accB[4], a.y, w4);
        fma2(accA[5], a.x, w5); fma2(accB[5], a.y, w5);
        fma2(accA[6], a.x, w6); fma2(accB[6], a.y, w6);
        fma2(accA[7], a.x, w7); fma2(accB[7], a.y, w7);
    }
}

// SMEM layout (floats):
#define OFS_WS0 0                      // [K0][8]   layer0 weights (rows = gate*2+unit)
#define OFS_WS1 2560                   // [K1][8]   layer1 weights
#define OFS_P0  6656                   // [8 kq][8 r][128 c] layer0 partials
#define OFS_P1  14848                  // [8 kq][8 r][128 c] layer1 partials
#define OFS_CST 23040                  // [2 l][2 u][128 c] cell state
#define OFS_BIA 23552                  // [2 l][8 r] biases
#define SM_FLOATS 23568                // >= 16448 needed by projection phase
#define SM_BYTES  (SM_FLOATS * 4)

extern "C" __global__ void __launch_bounds__(NTHR, 1)
lstm_persistent_kernel(const float* __restrict__ input,
                       const float* __restrict__ W_ih0, const float* __restrict__ W_hh0,
                       const float* __restrict__ b_ih0, const float* __restrict__ b_hh0,
                       const float* __restrict__ W_ih1, const float* __restrict__ W_hh1,
                       const float* __restrict__ b_ih1, const float* __restrict__ b_hh1,
                       const float* __restrict__ W_lin, const float* __restrict__ b_lin,
                       float* __restrict__ out)
{
    extern __shared__ float sm[];
    const int cta  = blockIdx.x;
    const int tid  = threadIdx.x;
    const int w    = tid >> 5;         // 0..7 layer0 k-eighths, 8..15 layer1 k-eighths
    const int lane = tid & 31;

    unsigned rel_base = *(volatile unsigned*)&g_release;   // quiescent at launch start
    unsigned barn = 0;

    // ---- Phase 0: init state, stage weights, transpose input ----
    for (int i = tid; i < 512; i += NTHR) sm[OFS_CST + i] = 0.f;
    for (int i = cta * NTHR + tid; i < 2 * HH * BB; i += NCTA * NTHR) {
        g_h0[i] = 0.f;
        g_h1[i] = 0.f;
    }
    // ws0[k*8 + r] = W0[(r>>1)*HH + 2*cta + (r&1)][k], k<INF from W_ih0 else W_hh0
    for (int i = tid; i < K0 * 8; i += NTHR) {
        int k = i >> 3, r = i & 7;
        int row = (r >> 1) * HH + 2 * cta + (r & 1);
        sm[OFS_WS0 + i] = (k < INF) ? W_ih0[row * INF + k] : W_hh0[row * HH + (k - INF)];
    }
    for (int i = tid; i < K1 * 8; i += NTHR) {
        int k = i >> 3, r = i & 7;
        int row = (r >> 1) * HH + 2 * cta + (r & 1);
        sm[OFS_WS1 + i] = (k < HH) ? W_ih1[row * HH + k] : W_hh1[row * HH + (k - HH)];
    }
    if (tid < 16) {
        int l = tid >> 3, r = tid & 7;
        int row = (r >> 1) * HH + 2 * cta + (r & 1);
        sm[OFS_BIA + tid] = l ? (b_ih1[row] + b_hh1[row]) : (b_ih0[row] + b_hh0[row]);
    }
    // transpose this CTA's 8 timesteps: XT[t][i][b] = input[b][t][i]
    for (int t = cta * 8; t < cta * 8 + 8; t++) {
        for (int i = tid; i < INF * BB; i += NTHR) {
            int ii = i >> 7, b = i & 127;
            g_XT[t * INF * BB + ii * BB + b] = input[(size_t)b * TT * INF + t * INF + ii];
        }
    }
    grid_bar(rel_base, barn);

    const float4* ws4 = reinterpret_cast<const float4*>(sm + ((w < 8) ? OFS_WS0 : OFS_WS1));
    float* pbase = sm + ((w < 8) ? OFS_P0 : OFS_P1) + (w & 7) * 1024;  // [kq][r][c]

    // ew role: tid<128: layer l, unit j, 4 cols starting c
    const int el = tid >> 6;
    const int ej = (tid >> 5) & 1;
    const int ec = (tid & 31) * 4;

    // ---- Main loop: tick tau = layer0(tau) + layer1(tau-1); one barrier/tick ----
    for (int tau = 0; tau <= TT; tau++) {
        const int pw = tau & 1;
        const int pr = pw ^ 1;

        ull accA[8], accB[8];
#pragma unroll
        for (int r = 0; r < 8; r++) { accA[r] = 0ull; accB[r] = 0ull; }

        bool did = false;
        if (w < 8) {
            if (tau < TT) {
                did = true;
                const int ks = w * 40, ke = ks + 40;     // 8 x 40 = K0
                if (ks < INF)   // x segment
                    gemm_seg(accA, accB, ws4, ks, min(ke, INF),
                             g_XT + tau * INF * BB, 0, lane);
                if (ke > INF)   // h0(tau-1) segment
                    gemm_seg(accA, accB, ws4, max(ks, INF), ke,
                             g_h0 + pr * HH * BB, INF, lane);
            }
        } else {
            if (tau >= 1) {
                did = true;
                const int kq = w - 8;
                const int ks = kq * 64, ke = ks + 64;    // 8 x 64 = K1
                if (kq < 4)     // h0(tau-1) half
                    gemm_seg(accA, accB, ws4, ks, ke, g_h0 + pr * HH * BB, 0, lane);
                else            // h1(tau-2) half
                    gemm_seg(accA, accB, ws4, ks, ke, g_h1 + pw * HH * BB, HH, lane);
            }
        }
        if (did) {
#pragma unroll
            for (int r = 0; r < 8; r++) {
                ulonglong2 v; v.x = accA[r]; v.y = accB[r];
                *reinterpret_cast<ulonglong2*>(pbase + r * 128 + 4 * lane) = v;
            }
        }
        __syncthreads();

        // elementwise: combine 8 k-partials, apply gates, update c/h
        if (tid < 128) {
            const bool doit = (el == 0) ? (tau < TT) : (tau >= 1);
            if (doit) {
                const float* pb = sm + (el ? OFS_P1 : OFS_P0);
                float4 gs[4];
#pragma unroll
                for (int g = 0; g < 4; g++) {
                    const int roff = (g * 2 + ej) * 128 + ec;
                    float4 s = *reinterpret_cast<const float4*>(pb + roff);
#pragma unroll
                    for (int q = 1; q < 8; q++) {
                        float4 sq = *reinterpret_cast<const float4*>(pb + q * 1024 + roff);
                        s.x += sq.x; s.y += sq.y; s.z += sq.z; s.w += sq.w;
                    }
                    const float bv = sm[OFS_BIA + el * 8 + g * 2 + ej];
                    gs[g].x = s.x + bv; gs[g].y = s.y + bv;
                    gs[g].z = s.z + bv; gs[g].w = s.w + bv;
                }
                float4 c_old = *reinterpret_cast<float4*>(sm + OFS_CST + (el * 2 + ej) * 128 + ec);
                float4 cn, hn;
                cn.x = sigf(gs[1].x) * c_old.x + sigf(gs[0].x) * tanhf(gs[2].x);
                cn.y = sigf(gs[1].y) * c_old.y + sigf(gs[0].y) * tanhf(gs[2].y);
                cn.z = sigf(gs[1].z) * c_old.z + sigf(gs[0].z) * tanhf(gs[2].z);
                cn.w = sigf(gs[1].w) * c_old.w + sigf(gs[0].w) * tanhf(gs[2].w);
                *reinterpret_cast<float4*>(sm + OFS_CST + (el * 2 + ej) * 128 + ec) = cn;
                hn.x = sigf(gs[3].x) * tanhf(cn.x);
                hn.y = sigf(gs[3].y) * tanhf(cn.y);
                hn.z = sigf(gs[3].z) * tanhf(cn.z);
                hn.w = sigf(gs[3].w) * tanhf(cn.w);
                const int row = 2 * cta + ej;
                if (el == 0) {
                    __stcg(reinterpret_cast<float4*>(g_h0 + pw * HH * BB + row * BB + ec), hn);
                } else {
                    __stcg(reinterpret_cast<float4*>(g_h1 + pr * HH * BB + row * BB + ec), hn);
                    __stcg(reinterpret_cast<float4*>(g_H1 + (size_t)(tau - 1) * HH * BB + row * BB + ec), hn);
                }
            }
        }
        grid_bar(rel_base, barn);
    }

    // ---- Deferred projection: out[b][t][o] = h1(t) . W_lin[o] + b_lin[o] ----
    for (int i = tid; i < OUTF * HH; i += NTHR) sm[i] = W_lin[i];
    if (tid < OUTF) sm[OUTF * HH + tid] = b_lin[tid];
    __syncthreads();

    // 16 warps: warp w handles timestep cta*8 + (w&7), output block (w>>3)*32..+32
    const int t = cta * 8 + (w & 7);
    const int obase = (w >> 3) * 32;
    const int bb4 = lane * 4;
    const float* hb = g_H1 + (size_t)t * HH * BB;
    for (int ob = obase; ob < obase + 32; ob += 8) {
        float acc[8][4];
#pragma unroll
        for (int oo = 0; oo < 8; oo++) { acc[oo][0] = acc[oo][1] = acc[oo][2] = acc[oo][3] = 0.f; }
        for (int j = 0; j < HH; j++) {
            const float4 hv = *reinterpret_cast<const float4*>(hb + j * BB + bb4);
#pragma unroll
            for (int oo = 0; oo < 8; oo++) {
                const float wv = sm[(ob + oo) * HH + j];
                acc[oo][0] += wv * hv.x; acc[oo][1] += wv * hv.y;
                acc[oo][2] += wv * hv.z; acc[oo][3] += wv * hv.w;
            }
        }
#pragma unroll
        for (int oo = 0; oo < 8; oo++) {
            const int o = ob + oo;
            const float bl = sm[OUTF * HH + o];
            out[(size_t)(bb4 + 0) * TT * OUTF + t * OUTF + o] = acc[oo][0] + bl;
            out[(size_t)(bb4 + 1) * TT * OUTF + t * OUTF + o] = acc[oo][1] + bl;
            out[(size_t)(bb4 + 2) * TT * OUTF + t * OUTF + o] = acc[oo][2] + bl;
            out[(size_t)(bb4 + 3) * TT * OUTF + t * OUTF + o] = acc[oo][3] + bl;
        }
    }
}

extern "C" void kernel_launch(void* const* d_in, const int* in_sizes, int n_in,
                              void* d_out, int out_size)
{
    (void)in_sizes; (void)n_in; (void)out_size;
    cudaFuncSetAttribute(lstm_persistent_kernel,
                         cudaFuncAttributeMaxDynamicSharedMemorySize, SM_BYTES);
    lstm_persistent_kernel<<<NCTA, NTHR, SM_BYTES>>>(
        (const float*)d_in[0],
        (const float*)d_in[1], (const float*)d_in[2],
        (const float*)d_in[3], (const float*)d_in[4],
        (const float*)d_in[5], (const float*)d_in[6],
        (const float*)d_in[7], (const float*)d_in[8],
        (const float*)d_in[9], (const float*)d_in[10],
        (float*)d_out);
}

// round 7
// speedup vs baseline: 2.9053x; 1.0554x over previous
#include <cuda_runtime.h>

#define BB   128          // batch
#define TT   1024         // time steps
#define INF  64           // input features
#define HH   256          // hidden (both layers)
#define OUTF 64           // output features
#define NCTA 128
#define NTHR 512
#define K0   (INF + HH)   // 320
#define K1   (2 * HH)     // 512

typedef unsigned long long ull;

// Persistent device state (static allocs allowed; no cudaMalloc anywhere)
__device__ __align__(16) float g_XT[TT * INF * BB];   // input transposed [t][i][b]
__device__ __align__(16) float g_h0[2 * HH * BB];     // layer0 h double-buffered [p][k][b]
__device__ __align__(16) float g_h1[2 * HH * BB];     // layer1 h double-buffered
__device__ __align__(16) float g_H1[TT * HH * BB];    // all layer1 h (deferred projection)
__device__ unsigned g_arrive = 0;                     // PROVEN ticket-barrier counters
__device__ unsigned g_release = 0;

__device__ __forceinline__ float sigf(float x) { return 1.0f / (1.0f + __expf(-x)); }

// PROVEN monotonic-ticket grid barrier (byte-exact semantics from the passing kernels).
__device__ __forceinline__ void grid_bar(unsigned rel_base, unsigned& barn)
{
    __syncthreads();
    if (threadIdx.x == 0) {
        __threadfence();
        barn++;
        unsigned prev = atomicAdd(&g_arrive, 1u);
        if (((prev + 1u) & (NCTA - 1u)) == 0u) {
            atomicAdd(&g_release, 1u);
        } else {
            unsigned need = rel_base + barn;
            while ((int)(*(volatile unsigned*)&g_release - need) < 0) { }
        }
        __threadfence();
    }
    __syncthreads();
}

// packed dual fp32 FMA: acc(lo,hi) += a(lo,hi) * b(lo,hi)
__device__ __forceinline__ void fma2(ull& acc, ull a, ull b)
{
    asm("fma.rn.f32x2 %0, %1, %2, %0;" : "+l"(acc) : "l"(a), "l"(b));
}
// splat float into both halves of a 64-bit pair (ALU pipe)
__device__ __forceinline__ ull pk(float x)
{
    ull r; asm("mov.b64 %0, {%1, %1};" : "=l"(r) : "f"(x)); return r;
}

// Inner GEMM with software-pipelined prefetch: 8 gate rows x 4 cols/lane,
// k in [ks,ke), (ke-ks) % 4 == 0. Buffer j holds group's slot j; while
// consuming slot j we issue the load for the NEXT group's slot j, so L2
// latency overlaps the current group's 27-instr compute (round-7 change).
__device__ __forceinline__ void gemm_seg(ull* accA, ull* accB,
                                         const float4* __restrict__ ws4,
                                         int ks, int ke,
                                         const float* __restrict__ act, int koff, int lane)
{
    const ulonglong2* ap = reinterpret_cast<const ulonglong2*>(act) + lane;
    ulonglong2 buf[4];
#pragma unroll
    for (int j = 0; j < 4; j++)
        buf[j] = __ldcg(ap + (ks + j - koff) * (BB / 4));

    for (int k = ks; k < ke; k += 4) {
#pragma unroll
        for (int j = 0; j < 4; j++) {
            const ulonglong2 a = buf[j];
            const int kn = k + 4 + j;                    // prefetch next group, slot j
            if (kn < ke) buf[j] = __ldcg(ap + (kn - koff) * (BB / 4));
            const float4 wlo = ws4[(k + j) * 2 + 0];
            const float4 whi = ws4[(k + j) * 2 + 1];
            const ull w0 = pk(wlo.x), w1 = pk(wlo.y), w2 = pk(wlo.z), w3 = pk(wlo.w);
            const ull w4 = pk(whi.x), w5 = pk(whi.y), w6 = pk(whi.z), w7 = pk(whi.w);
            fma2(accA[0], a.x, w0); fma2(accB[0], a.y, w0);
            fma2(accA[1], a.x, w1); fma2(accB[1], a.y, w1);
            fma2(accA[2], a.x, w2); fma2(accB[2], a.y, w2);
            fma2(accA[3], a.x, w3); fma2(accB[3], a.y, w3);
            fma2(accA[4], a.x, w4); fma2(accB[4], a.y, w4);
            fma2(accA[5], a.x, w5); fma2(accB[5], a.y, w5);
            fma2(accA[6], a.x, w6); fma2(accB[6], a.y, w6);
            fma2(accA[7], a.x, w7); fma2(accB[7], a.y, w7);
        }
    }
}

// SMEM layout (floats):
#define OFS_WS0 0                      // [K0][8]   layer0 weights (rows = gate*2+unit)
#define OFS_WS1 2560                   // [K1][8]   layer1 weights
#define OFS_P0  6656                   // [8 kq][8 r][128 c] layer0 partials
#define OFS_P1  14848                  // [8 kq][8 r][128 c] layer1 partials
#define OFS_CST 23040                  // [2 l][2 u][128 c] cell state
#define OFS_BIA 23552                  // [2 l][8 r] biases
#define SM_FLOATS 23568                // >= 16448 needed by projection phase
#define SM_BYTES  (SM_FLOATS * 4)

extern "C" __global__ void __launch_bounds__(NTHR, 1)
lstm_persistent_kernel(const float* __restrict__ input,
                       const float* __restrict__ W_ih0, const float* __restrict__ W_hh0,
                       const float* __restrict__ b_ih0, const float* __restrict__ b_hh0,
                       const float* __restrict__ W_ih1, const float* __restrict__ W_hh1,
                       const float* __restrict__ b_ih1, const float* __restrict__ b_hh1,
                       const float* __restrict__ W_lin, const float* __restrict__ b_lin,
                       float* __restrict__ out)
{
    extern __shared__ float sm[];
    const int cta  = blockIdx.x;
    const int tid  = threadIdx.x;
    const int w    = tid >> 5;         // 0..7 layer0 k-eighths, 8..15 layer1 k-eighths
    const int lane = tid & 31;

    unsigned rel_base = *(volatile unsigned*)&g_release;   // quiescent at launch start
    unsigned barn = 0;

    // ---- Phase 0: init state, stage weights, transpose input ----
    for (int i = tid; i < 512; i += NTHR) sm[OFS_CST + i] = 0.f;
    for (int i = cta * NTHR + tid; i < 2 * HH * BB; i += NCTA * NTHR) {
        g_h0[i] = 0.f;
        g_h1[i] = 0.f;
    }
    // ws0[k*8 + r] = W0[(r>>1)*HH + 2*cta + (r&1)][k], k<INF from W_ih0 else W_hh0
    for (int i = tid; i < K0 * 8; i += NTHR) {
        int k = i >> 3, r = i & 7;
        int row = (r >> 1) * HH + 2 * cta + (r & 1);
        sm[OFS_WS0 + i] = (k < INF) ? W_ih0[row * INF + k] : W_hh0[row * HH + (k - INF)];
    }
    for (int i = tid; i < K1 * 8; i += NTHR) {
        int k = i >> 3, r = i & 7;
        int row = (r >> 1) * HH + 2 * cta + (r & 1);
        sm[OFS_WS1 + i] = (k < HH) ? W_ih1[row * HH + k] : W_hh1[row * HH + (k - HH)];
    }
    if (tid < 16) {
        int l = tid >> 3, r = tid & 7;
        int row = (r >> 1) * HH + 2 * cta + (r & 1);
        sm[OFS_BIA + tid] = l ? (b_ih1[row] + b_hh1[row]) : (b_ih0[row] + b_hh0[row]);
    }
    // transpose this CTA's 8 timesteps: XT[t][i][b] = input[b][t][i]
    for (int t = cta * 8; t < cta * 8 + 8; t++) {
        for (int i = tid; i < INF * BB; i += NTHR) {
            int ii = i >> 7, b = i & 127;
            g_XT[t * INF * BB + ii * BB + b] = input[(size_t)b * TT * INF + t * INF + ii];
        }
    }
    grid_bar(rel_base, barn);

    const float4* ws4 = reinterpret_cast<const float4*>(sm + ((w < 8) ? OFS_WS0 : OFS_WS1));
    float* pbase = sm + ((w < 8) ? OFS_P0 : OFS_P1) + (w & 7) * 1024;  // [kq][r][c]

    // ew role: tid<128: layer l, unit j, 4 cols starting c
    const int el = tid >> 6;
    const int ej = (tid >> 5) & 1;
    const int ec = (tid & 31) * 4;

    // ---- Main loop: tick tau = layer0(tau) + layer1(tau-1); one barrier/tick ----
    for (int tau = 0; tau <= TT; tau++) {
        const int pw = tau & 1;
        const int pr = pw ^ 1;

        ull accA[8], accB[8];
#pragma unroll
        for (int r = 0; r < 8; r++) { accA[r] = 0ull; accB[r] = 0ull; }

        bool did = false;
        if (w < 8) {
            if (tau < TT) {
                did = true;
                const int ks = w * 40, ke = ks + 40;     // 8 x 40 = K0
                if (ks < INF)   // x segment
                    gemm_seg(accA, accB, ws4, ks, min(ke, INF),
                             g_XT + tau * INF * BB, 0, lane);
                if (ke > INF)   // h0(tau-1) segment
                    gemm_seg(accA, accB, ws4, max(ks, INF), ke,
                             g_h0 + pr * HH * BB, INF, lane);
            }
        } else {
            if (tau >= 1) {
                did = true;
                const int kq = w - 8;
                const int ks = kq * 64, ke = ks + 64;    // 8 x 64 = K1
                if (kq < 4)     // h0(tau-1) half
                    gemm_seg(accA, accB, ws4, ks, ke, g_h0 + pr * HH * BB, 0, lane);
                else            // h1(tau-2) half
                    gemm_seg(accA, accB, ws4, ks, ke, g_h1 + pw * HH * BB, HH, lane);
            }
        }
        if (did) {
#pragma unroll
            for (int r = 0; r < 8; r++) {
                ulonglong2 v; v.x = accA[r]; v.y = accB[r];
                *reinterpret_cast<ulonglong2*>(pbase + r * 128 + 4 * lane) = v;
            }
        }
        __syncthreads();

        // elementwise: combine 8 k-partials, apply gates, update c/h
        if (tid < 128) {
            const bool doit = (el == 0) ? (tau < TT) : (tau >= 1);
            if (doit) {
                const float* pb = sm + (el ? OFS_P1 : OFS_P0);
                float4 gs[4];
#pragma unroll
                for (int g = 0; g < 4; g++) {
                    const int roff = (g * 2 + ej) * 128 + ec;
                    float4 s = *reinterpret_cast<const float4*>(pb + roff);
#pragma unroll
                    for (int q = 1; q < 8; q++) {
                        float4 sq = *reinterpret_cast<const float4*>(pb + q * 1024 + roff);
                        s.x += sq.x; s.y += sq.y; s.z += sq.z; s.w += sq.w;
                    }
                    const float bv = sm[OFS_BIA + el * 8 + g * 2 + ej];
                    gs[g].x = s.x + bv; gs[g].y = s.y + bv;
                    gs[g].z = s.z + bv; gs[g].w = s.w + bv;
                }
                float4 c_old = *reinterpret_cast<float4*>(sm + OFS_CST + (el * 2 + ej) * 128 + ec);
                float4 cn, hn;
                cn.x = sigf(gs[1].x) * c_old.x + sigf(gs[0].x) * tanhf(gs[2].x);
                cn.y = sigf(gs[1].y) * c_old.y + sigf(gs[0].y) * tanhf(gs[2].y);
                cn.z = sigf(gs[1].z) * c_old.z + sigf(gs[0].z) * tanhf(gs[2].z);
                cn.w = sigf(gs[1].w) * c_old.w + sigf(gs[0].w) * tanhf(gs[2].w);
                *reinterpret_cast<float4*>(sm + OFS_CST + (el * 2 + ej) * 128 + ec) = cn;
                hn.x = sigf(gs[3].x) * tanhf(cn.x);
                hn.y = sigf(gs[3].y) * tanhf(cn.y);
                hn.z = sigf(gs[3].z) * tanhf(cn.z);
                hn.w = sigf(gs[3].w) * tanhf(cn.w);
                const int row = 2 * cta + ej;
                if (el == 0) {
                    __stcg(reinterpret_cast<float4*>(g_h0 + pw * HH * BB + row * BB + ec), hn);
                } else {
                    __stcg(reinterpret_cast<float4*>(g_h1 + pr * HH * BB + row * BB + ec), hn);
                    __stcg(reinterpret_cast<float4*>(g_H1 + (size_t)(tau - 1) * HH * BB + row * BB + ec), hn);
                }
            }
        }
        grid_bar(rel_base, barn);
    }

    // ---- Deferred projection: out[b][t][o] = h1(t) . W_lin[o] + b_lin[o] ----
    for (int i = tid; i < OUTF * HH; i += NTHR) sm[i] = W_lin[i];
    if (tid < OUTF) sm[OUTF * HH + tid] = b_lin[tid];
    __syncthreads();

    // 16 warps: warp w handles timestep cta*8 + (w&7), output block (w>>3)*32..+32
    const int t = cta * 8 + (w & 7);
    const int obase = (w >> 3) * 32;
    const int bb4 = lane * 4;
    const float* hb = g_H1 + (size_t)t * HH * BB;
    for (int ob = obase; ob < obase + 32; ob += 8) {
        float acc[8][4];
#pragma unroll
        for (int oo = 0; oo < 8; oo++) { acc[oo][0] = acc[oo][1] = acc[oo][2] = acc[oo][3] = 0.f; }
        for (int j = 0; j < HH; j++) {
            const float4 hv = *reinterpret_cast<const float4*>(hb + j * BB + bb4);
#pragma unroll
            for (int oo = 0; oo < 8; oo++) {
                const float wv = sm[(ob + oo) * HH + j];
                acc[oo][0] += wv * hv.x; acc[oo][1] += wv * hv.y;
                acc[oo][2] += wv * hv.z; acc[oo][3] += wv * hv.w;
            }
        }
#pragma unroll
        for (int oo = 0; oo < 8; oo++) {
            const int o = ob + oo;
            const float bl = sm[OUTF * HH + o];
            out[(size_t)(bb4 + 0) * TT * OUTF + t * OUTF + o] = acc[oo][0] + bl;
            out[(size_t)(bb4 + 1) * TT * OUTF + t * OUTF + o] = acc[oo][1] + bl;
            out[(size_t)(bb4 + 2) * TT * OUTF + t * OUTF + o] = acc[oo][2] + bl;
            out[(size_t)(bb4 + 3) * TT * OUTF + t * OUTF + o] = acc[oo][3] + bl;
        }
    }
}

extern "C" void kernel_launch(void* const* d_in, const int* in_sizes, int n_in,
                              void* d_out, int out_size)
{
    (void)in_sizes; (void)n_in; (void)out_size;
    cudaFuncSetAttribute(lstm_persistent_kernel,
                         cudaFuncAttributeMaxDynamicSharedMemorySize, SM_BYTES);
    lstm_persistent_kernel<<<NCTA, NTHR, SM_BYTES>>>(
        (const float*)d_in[0],
        (const float*)d_in[1], (const float*)d_in[2],
        (const float*)d_in[3], (const float*)d_in[4],
        (const float*)d_in[5], (const float*)d_in[6],
        (const float*)d_in[7], (const float*)d_in[8],
        (const float*)d_in[9], (const float*)d_in[10],
        (float*)d_out);
}